// round 16
// baseline (speedup 1.0000x reference)
#include <cuda_runtime.h>
#include <cuda_fp16.h>
#include <math.h>
#include <stdint.h>

#define BB 8
#define NN 512
#define TT 64
#define NIN 64
#define NE 128
#define NH 128
#define NZ 512
#define NODES (BB*NN)   // 4096

// ---------------- persistent device scratch ----------------
__device__ float g_dinv[BB*NN];
__device__ __half g_An[BB*NN*NN];        // fp16 single
__device__ __half g_h[2][NODES*NH];      // fp16 single, ping-pong
__device__ float g_es[NODES*NE];
__device__ float g_esW[NODES*NZ];
__device__ float g_b0[NZ];
__device__ __half g_Wz[256*NZ];          // [k][n], fp16 single
__device__ __half g_Wo_hi[NH*NIN], g_Wo_lo[NH*NIN];   // [k][n] split fp16
__device__ int g_barc[BB];
__device__ int g_barg[BB];

// ---------------- helpers ----------------
__device__ __forceinline__ uint32_t smem_u32(const void* p) {
    uint32_t a;
    asm("{ .reg .u64 t; cvta.to.shared.u64 t, %1; cvt.u32.u64 %0, t; }" : "=r"(a) : "l"(p));
    return a;
}
__device__ __forceinline__ void ldsm4(uint32_t* r, uint32_t addr) {
    asm volatile("ldmatrix.sync.aligned.m8n8.x4.shared.b16 {%0,%1,%2,%3}, [%4];"
        : "=r"(r[0]), "=r"(r[1]), "=r"(r[2]), "=r"(r[3]) : "r"(addr));
}
__device__ __forceinline__ void ldsm4t(uint32_t* r, uint32_t addr) {
    asm volatile("ldmatrix.sync.aligned.m8n8.x4.trans.shared.b16 {%0,%1,%2,%3}, [%4];"
        : "=r"(r[0]), "=r"(r[1]), "=r"(r[2]), "=r"(r[3]) : "r"(addr));
}
__device__ __forceinline__ void ldsm2t(uint32_t* r, uint32_t addr) {
    asm volatile("ldmatrix.sync.aligned.m8n8.x2.trans.shared.b16 {%0,%1}, [%2];"
        : "=r"(r[0]), "=r"(r[1]) : "r"(addr));
}
__device__ __forceinline__ void mma_f16(float* d, const uint32_t* a, const uint32_t* b) {
    asm volatile("mma.sync.aligned.m16n8k16.row.col.f32.f16.f16.f32 "
        "{%0,%1,%2,%3}, {%4,%5,%6,%7}, {%8,%9}, {%0,%1,%2,%3};"
        : "+f"(d[0]), "+f"(d[1]), "+f"(d[2]), "+f"(d[3])
        : "r"(a[0]), "r"(a[1]), "r"(a[2]), "r"(a[3]), "r"(b[0]), "r"(b[1]));
}
__device__ __forceinline__ void split_h(float x, __half& h, __half& l) {
    h = __float2half_rn(x);
    l = __float2half_rn(x - __half2float(h));
}
__device__ __forceinline__ float sigf(float x) { return 1.f / (1.f + __expf(-x)); }

// ---------------- setup kernels ----------------
__global__ void k_dinv(const float* __restrict__ A) {
    int row = blockIdx.x;
    const float* ap = A + (size_t)row * NN;
    float s = 0.f;
    for (int i = threadIdx.x; i < NN; i += 128) s += ap[i];
    __shared__ float red[4];
    for (int o = 16; o; o >>= 1) s += __shfl_xor_sync(0xffffffffu, s, o);
    if ((threadIdx.x & 31) == 0) red[threadIdx.x >> 5] = s;
    __syncthreads();
    if (threadIdx.x == 0) {
        float d = red[0] + red[1] + red[2] + red[3];
        g_dinv[row] = d > 0.f ? rsqrtf(d) : 0.f;
    }
}

__global__ void k_an(const float* __restrict__ A) {
    int idx = blockIdx.x * 256 + threadIdx.x;
    int b = idx / (NN * NN);
    int r = (idx / NN) % NN;
    int m = idx % NN;
    float v = A[idx] * g_dinv[b * NN + r] * g_dinv[b * NN + m];
    g_An[idx] = __float2half_rn(v);
}

__global__ void k_es(const float* __restrict__ X, const float* __restrict__ Wse,
                     const float* __restrict__ bse, float* __restrict__ out) {
    int idx = blockIdx.x * 256 + threadIdx.x;
    int node = idx >> 7, j = idx & 127;
    const float* x0 = X + (size_t)node * TT * NIN;
    float acc = bse[j];
    #pragma unroll
    for (int q = 0; q < NIN; q++) acc += x0[q] * Wse[q * NE + j];
    g_es[idx] = acc;
    if (j < NIN) out[(size_t)node * TT * NIN + j] = x0[j];
}

__global__ void k_wz(const float* __restrict__ Wpe, const float* __restrict__ bpe,
    const float* __restrict__ Wii, const float* __restrict__ bii,
    const float* __restrict__ Whi, const float* __restrict__ bhi,
    const float* __restrict__ Wif, const float* __restrict__ bif,
    const float* __restrict__ Whf, const float* __restrict__ bhf,
    const float* __restrict__ Wig, const float* __restrict__ big,
    const float* __restrict__ Whg, const float* __restrict__ bhg,
    const float* __restrict__ Wio, const float* __restrict__ bio,
    const float* __restrict__ Who, const float* __restrict__ bho) {
    int idx = blockIdx.x * 256 + threadIdx.x;   // [k][n]
    int k = idx >> 9, n = idx & 511;
    int ch = n >> 2, g = n & 3;
    const float* Wg  = g == 0 ? Wii : g == 1 ? Wif : g == 2 ? Wig : Wio;
    const float* Whx = g == 0 ? Whi : g == 1 ? Whf : g == 2 ? Whg : Who;
    float v;
    if (k < 128) {
        v = 0.f;
        for (int p = 0; p < NE; p++) v += Wpe[k * NE + p] * Wg[(NE + p) * NH + ch];
    } else {
        v = Whx[(k - 128) * NH + ch];
    }
    g_Wz[idx] = __float2half_rn(v);
    if (k == 0) {
        const float* bg  = g == 0 ? bii : g == 1 ? bif : g == 2 ? big : bio;
        const float* bhx = g == 0 ? bhi : g == 1 ? bhf : g == 2 ? bhg : bho;
        float bv = bg[ch] + bhx[ch];
        for (int p = 0; p < NE; p++) bv += bpe[p] * Wg[(NE + p) * NH + ch];
        g_b0[n] = bv;
    }
}

__global__ void k_esw(const float* __restrict__ Wii, const float* __restrict__ Wif,
                      const float* __restrict__ Wig, const float* __restrict__ Wio) {
    int idx = blockIdx.x * 256 + threadIdx.x;
    int node = idx >> 9, j = idx & 511;
    int ch = j >> 2, g = j & 3;
    const float* Wg = g == 0 ? Wii : g == 1 ? Wif : g == 2 ? Wig : Wio;
    const float* e = g_es + (size_t)node * NE;
    float acc = g_b0[j];
    for (int p = 0; p < NE; p++) acc += e[p] * Wg[p * NH + ch];
    g_esW[idx] = acc;
}

__global__ void k_wo(const float* __restrict__ Wout) {
    int idx = blockIdx.x * 256 + threadIdx.x;   // NH*NIN, [k][n]
    split_h(Wout[idx], g_Wo_hi[idx], g_Wo_lo[idx]);
}

__global__ void k_zero() {
    int idx = blockIdx.x * 256 + threadIdx.x;
    g_h[0][idx] = __float2half(0.f);
    if (idx < BB) { g_barc[idx] = 0; g_barg[idx] = 0; }
}

// ---------------- smem layout (bytes), 114944 total (2 CTAs/SM) ----------------
#define S_AN      0u          // [16][520] fp16 (resident)
#define S_HH_HI   16640u      // [16][264] fp16: cols 0-127 H/hn_hi, 128-255 own h
#define S_HH_LO   25088u      // [16][136] fp16 (hn_lo for phase C)
#define S_W       29440u      // 2 x [32][264] fp16 (phase B dbl-buf); phase C Wo_hi [128][72]
#define WB(s)     (S_W + (s) * 16896u)
#define S_HC      63232u      // phase A h chunk [128][136] fp16; phase B zb [16][260] f32; phase C Wo_lo [128][72]
#define S_HN      98048u      // [16][132] f32 (resident)
#define S_SC      106496u     // [16][132] f32 (resident c state)
#define SMEM_TOT  114944

// ---------------- persistent all-steps kernel ----------------
// grid 256 (node tiles of 16; 2 CTAs/SM; 32 CTAs per batch), block 256 (8 warps)
__global__ __launch_bounds__(256, 2) void k_steps(const float* __restrict__ bout,
                                                  float* __restrict__ out) {
    extern __shared__ char sm[];
    uint32_t smb = smem_u32(sm);
    int tid = threadIdx.x, lane = tid & 31, wn = tid >> 5;   // 8 warps = 8 n-strips
    long node0 = (long)blockIdx.x * 16;
    int b = (int)(node0 >> 9);

    int a_r = (lane & 7) + ((lane >> 3) & 1) * 8;
    int a_c = ((lane >> 4) & 1) * 8;
    int bt_r = lane & 15;
    int bt_c = ((lane >> 4) & 1) * 8;

    float* zb = (float*)(sm + S_HC);
    float* hn = (float*)(sm + S_HN);
    float* sc = (float*)(sm + S_SC);

    // ---- one-time init ----
    #pragma unroll
    for (int i = 0; i < 4; i++) {
        int idx = i * 256 + tid;
        int row = idx >> 6, seg = idx & 63;
        *(uint4*)(sm + S_AN + (row * 520 + seg * 8) * 2) =
            *((const uint4*)(g_An + (node0 + row) * (long)NN) + seg);
    }
    for (int i = tid; i < 16 * 132; i += 256) { sc[i] = 0.f; hn[i] = 0.f; }
    int pcol = wn * 8 + (lane & 3) * 2;
    float b0v = bout[pcol], b1v = bout[pcol + 1];
    int cr0 = lane >> 2, cr1 = cr0 + 8;
    float2 orun0 = *(const float2*)(out + ((node0 + cr0) * TT) * NIN + pcol);
    float2 orun1 = *(const float2*)(out + ((node0 + cr1) * TT) * NIN + pcol);
    __syncthreads();

    for (int t = 1; t < TT; t++) {
        int pp = (t + 1) & 1, pn = t & 1;
        const __half* hp = g_h[pp];
        bool last = (t == TT - 1);

        // ---- own h (resident hn) -> HH cols 128-255; prefetch W tile 0 -> WB(0) ----
        {
            int row = tid >> 4, seg = tid & 15;
            const float* hr = hn + row * 132 + seg * 8;
            __half hh[8];
            #pragma unroll
            for (int j = 0; j < 8; j++) hh[j] = __float2half_rn(hr[j]);
            *(uint4*)(sm + S_HH_HI + (row * 264 + 128 + seg * 8) * 2) = *(const uint4*)hh;
            #pragma unroll
            for (int i = 0; i < 4; i++) {
                int idx = i * 256 + tid;
                int wrow = idx >> 5, wseg = idx & 31;
                *(uint4*)(sm + WB(0) + (wrow * 264 + wseg * 8) * 2) =
                    *(const uint4*)(g_Wz + (long)wrow * NZ + wseg * 8);
            }
        }

        // ---- Phase A: H = An(resident) @ h (4 K-chunks of 128) ----
        float accA[2][4];
        #pragma unroll
        for (int nt = 0; nt < 2; nt++)
            #pragma unroll
            for (int q = 0; q < 4; q++) accA[nt][q] = 0.f;

        {
            #pragma unroll
            for (int i = 0; i < 8; i++) {
                int idx = i * 256 + tid;
                int hr = idx >> 4, hs = idx & 15;
                uint4 v = __ldcg((const uint4*)(hp + ((long)b * NN + hr) * NH) + hs);
                *(uint4*)(sm + S_HC + (hr * 136 + hs * 8) * 2) = v;
            }
        }
        __syncthreads();

        for (int c = 0; c < 4; c++) {
            uint4 sh[8];
            if (c < 3) {
                #pragma unroll
                for (int i = 0; i < 8; i++) {
                    int idx = i * 256 + tid;
                    int hr = idx >> 4, hs = idx & 15;
                    sh[i] = __ldcg((const uint4*)(hp + ((long)b * NN + (c + 1) * 128 + hr) * NH) + hs);
                }
            }
            #pragma unroll
            for (int kk = 0; kk < 8; kk++) {
                uint32_t aH[4], b0[4];
                uint32_t aoff = (uint32_t)((a_r * 520 + c * 128 + kk * 16 + a_c) * 2);
                ldsm4(aH, smb + S_AN + aoff);
                uint32_t boff = (uint32_t)(((kk * 16 + bt_r) * 136 + wn * 16 + bt_c) * 2);
                ldsm4t(b0, smb + S_HC + boff);
                mma_f16(accA[0], aH, b0);
                mma_f16(accA[1], aH, b0 + 2);
            }
            __syncthreads();
            if (c < 3) {
                #pragma unroll
                for (int i = 0; i < 8; i++) {
                    int idx = i * 256 + tid;
                    int hr = idx >> 4, hs = idx & 15;
                    *(uint4*)(sm + S_HC + (hr * 136 + hs * 8) * 2) = sh[i];
                }
                __syncthreads();
            }
        }

        // ---- HH epilogue: H -> HH_HI cols 0-127 ----
        {
            #pragma unroll
            for (int nt = 0; nt < 2; nt++) {
                int col = wn * 16 + nt * 8 + (lane & 3) * 2;
                __half2 ph;
                ph.x = __float2half_rn(accA[nt][0]);
                ph.y = __float2half_rn(accA[nt][1]);
                *(__half2*)(sm + S_HH_HI + (cr0 * 264 + col) * 2) = ph;
                ph.x = __float2half_rn(accA[nt][2]);
                ph.y = __float2half_rn(accA[nt][3]);
                *(__half2*)(sm + S_HH_HI + (cr1 * 264 + col) * 2) = ph;
            }
        }
        __syncthreads();

        // ---- Phase B: z = esW + [H|h] @ Wz (16 W tiles of 32 rows, dbl-buffered) ----
        float accB[4][4];
        #pragma unroll
        for (int nt = 0; nt < 4; nt++)
            #pragma unroll
            for (int q = 0; q < 4; q++) accB[nt][q] = 0.f;

        for (int wt = 0; wt < 16; wt++) {
            int nc = wt >> 3, kc = wt & 7;
            uint4 stg[4];
            if (wt < 15) {
                int n2 = (wt + 1) >> 3, k2 = (wt + 1) & 7;
                #pragma unroll
                for (int i = 0; i < 4; i++) {
                    int idx = i * 256 + tid;
                    int row = idx >> 5, seg = idx & 31;
                    stg[i] = *(const uint4*)(g_Wz + (long)(k2 * 32 + row) * NZ + n2 * 256 + seg * 8);
                }
            }
            uint32_t wbuf = smb + WB(wt & 1);
            #pragma unroll
            for (int kk = 0; kk < 2; kk++) {
                uint32_t aH[4];
                uint32_t aoff = (uint32_t)((a_r * 264 + kc * 32 + kk * 16 + a_c) * 2);
                ldsm4(aH, smb + S_HH_HI + aoff);
                uint32_t bf[2][4];
                #pragma unroll
                for (int p = 0; p < 2; p++) {
                    uint32_t boff = (uint32_t)(((kk * 16 + bt_r) * 264 + wn * 32 + p * 16 + bt_c) * 2);
                    ldsm4t(bf[p], wbuf + boff);
                }
                mma_f16(accB[0], aH, bf[0]);
                mma_f16(accB[1], aH, bf[0] + 2);
                mma_f16(accB[2], aH, bf[1]);
                mma_f16(accB[3], aH, bf[1] + 2);
            }
            if (wt < 15) {
                uint32_t wb2 = WB((wt + 1) & 1);
                #pragma unroll
                for (int i = 0; i < 4; i++) {
                    int idx = i * 256 + tid;
                    int row = idx >> 5, seg = idx & 31;
                    *(uint4*)(sm + wb2 + (row * 264 + seg * 8) * 2) = stg[i];
                }
            }
            __syncthreads();

            if (kc == 7) {
                float4 e4s[4];
                {
                    int row = tid >> 4, g16 = tid & 15;
                    long node = node0 + row;
                    #pragma unroll
                    for (int q = 0; q < 4; q++)
                        e4s[q] = *(const float4*)(g_esW + node * NZ + nc * 256 + q * 64 + g16 * 4);
                }
                {
                    #pragma unroll
                    for (int nt = 0; nt < 4; nt++) {
                        int col = wn * 32 + nt * 8 + (lane & 3) * 2;
                        zb[cr0 * 260 + col]     = accB[nt][0];
                        zb[cr0 * 260 + col + 1] = accB[nt][1];
                        zb[cr1 * 260 + col]     = accB[nt][2];
                        zb[cr1 * 260 + col + 1] = accB[nt][3];
                        #pragma unroll
                        for (int q = 0; q < 4; q++) accB[nt][q] = 0.f;
                    }
                }
                __syncthreads();
                {
                    int row = tid >> 4, g16 = tid & 15;
                    #pragma unroll
                    for (int q = 0; q < 4; q++) {
                        int ch = nc * 64 + q * 16 + g16;
                        int colz = q * 64 + g16 * 4;
                        float4 z4 = *(const float4*)(zb + row * 260 + colz);
                        float4 e4 = e4s[q];
                        float it = sigf(z4.x + e4.x);
                        float ft = sigf(z4.y + e4.y);
                        float gt = tanhf(z4.z + e4.z);
                        float ot = sigf(z4.w + e4.w);
                        float cn = ft * sc[row * 132 + ch] + it * gt;
                        float hv = ot * tanhf(cn);
                        sc[row * 132 + ch] = cn;
                        hn[row * 132 + ch] = hv;
                    }
                }
                __syncthreads();
            }
        }

        // ---- writeback h(fp16, L2); stage hn split + Wo tiles ----
        {
            __half* hw = g_h[pn];
            #pragma unroll
            for (int i = 0; i < 2; i++) {
                int idx = i * 256 + tid;
                int row = idx >> 5, c4 = (idx & 31) * 4;
                long base = (node0 + row) * NH + c4;
                float4 hv4 = *(const float4*)(hn + row * 132 + c4);
                __half hh[4];
                hh[0] = __float2half_rn(hv4.x); hh[1] = __float2half_rn(hv4.y);
                hh[2] = __float2half_rn(hv4.z); hh[3] = __float2half_rn(hv4.w);
                __stcg((uint2*)(hw + base), *(const uint2*)hh);
            }
            #pragma unroll
            for (int i = 0; i < 4; i++) {
                int idx = i * 256 + tid;
                int row = idx >> 6, c2 = (idx & 63) * 2;
                float hv0 = hn[row * 132 + c2], hv1 = hn[row * 132 + c2 + 1];
                __half h0, l0, h1, l1;
                split_h(hv0, h0, l0); split_h(hv1, h1, l1);
                __half2 ph; ph.x = h0; ph.y = h1;
                __half2 pl; pl.x = l0; pl.y = l1;
                *(__half2*)(sm + S_HH_HI + (row * 264 + c2) * 2) = ph;
                *(__half2*)(sm + S_HH_LO + (row * 136 + c2) * 2) = pl;
            }
            #pragma unroll
            for (int i = 0; i < 4; i++) {
                int idx = i * 256 + tid;
                int row = idx >> 3, seg = idx & 7;
                *(uint4*)(sm + S_W + (row * 72 + seg * 8) * 2) =
                    *((const uint4*)(g_Wo_hi + row * NIN) + seg);
                *(uint4*)(sm + S_HC + (row * 72 + seg * 8) * 2) =
                    *((const uint4*)(g_Wo_lo + row * NIN) + seg);
            }
        }
        __threadfence();
        __syncthreads();

        // ---- EARLY per-batch arrive (h published); wait deferred past phase C ----
        if (!last && tid == 0) {
            int v = atomicAdd(&g_barc[b], 1);
            if (v == 32 * t - 1) atomicExch(&g_barg[b], t);
        }

        // ---- Phase C: out[t] = out[t-1](regs) + hn @ Wout + bout ----
        {
            float accC[4] = {0.f, 0.f, 0.f, 0.f};
            #pragma unroll
            for (int kk = 0; kk < 8; kk++) {
                uint32_t aH[4], aL[4], bH[2], bL[2];
                ldsm4(aH, smb + S_HH_HI + (uint32_t)((a_r * 264 + kk * 16 + a_c) * 2));
                ldsm4(aL, smb + S_HH_LO + (uint32_t)((a_r * 136 + kk * 16 + a_c) * 2));
                uint32_t boff = (uint32_t)(((kk * 16 + bt_r) * 72 + wn * 8) * 2);
                ldsm2t(bH, smb + S_W + boff);
                ldsm2t(bL, smb + S_HC + boff);
                mma_f16(accC, aH, bH);
                mma_f16(accC, aH, bL);
                mma_f16(accC, aL, bH);
            }
            orun0.x = (orun0.x + accC[0]) + b0v;
            orun0.y = (orun0.y + accC[1]) + b1v;
            orun1.x = (orun1.x + accC[2]) + b0v;
            orun1.y = (orun1.y + accC[3]) + b1v;
            long ob0 = (((node0 + cr0) * TT) + t) * NIN + pcol;
            long ob1 = (((node0 + cr1) * TT) + t) * NIN + pcol;
            *(float2*)(out + ob0) = orun0;
            *(float2*)(out + ob1) = orun1;
        }

        // ---- per-batch barrier wait (overlapped with phase C above) ----
        if (!last) {
            if (tid == 0) {
                while (*((volatile int*)&g_barg[b]) < t) { }
            }
            __syncthreads();
        }
    }
}

// ---------------- launch ----------------
extern "C" void kernel_launch(void* const* d_in, const int* in_sizes, int n_in,
                              void* d_out, int out_size) {
    (void)in_sizes; (void)n_in; (void)out_size;
    const float* X    = (const float*)d_in[0];
    const float* A    = (const float*)d_in[1];
    const float* Wse  = (const float*)d_in[2];
    const float* bse  = (const float*)d_in[3];
    const float* Wpe  = (const float*)d_in[4];
    const float* bpe  = (const float*)d_in[5];
    const float* Wii  = (const float*)d_in[6];
    const float* bii  = (const float*)d_in[7];
    const float* Whi  = (const float*)d_in[8];
    const float* bhi  = (const float*)d_in[9];
    const float* Wif  = (const float*)d_in[10];
    const float* bif  = (const float*)d_in[11];
    const float* Whf  = (const float*)d_in[12];
    const float* bhf  = (const float*)d_in[13];
    const float* Wig  = (const float*)d_in[14];
    const float* big  = (const float*)d_in[15];
    const float* Whg  = (const float*)d_in[16];
    const float* bhg  = (const float*)d_in[17];
    const float* Wio  = (const float*)d_in[18];
    const float* bio  = (const float*)d_in[19];
    const float* Who  = (const float*)d_in[20];
    const float* bho  = (const float*)d_in[21];
    const float* Wout = (const float*)d_in[22];
    const float* bout = (const float*)d_in[23];
    float* out = (float*)d_out;

    cudaFuncSetAttribute(k_steps, cudaFuncAttributeMaxDynamicSharedMemorySize, SMEM_TOT);

    k_dinv<<<BB * NN, 128>>>(A);
    k_an<<<(BB * NN * NN) / 256, 256>>>(A);
    k_es<<<(NODES * NE) / 256, 256>>>(X, Wse, bse, out);
    k_wz<<<(256 * NZ) / 256, 256>>>(Wpe, bpe, Wii, bii, Whi, bhi, Wif, bif,
                                    Whf, bhf, Wig, big, Whg, bhg,
                                    Wio, bio, Who, bho);
    k_esw<<<(NODES * NZ) / 256, 256>>>(Wii, Wif, Wig, Wio);
    k_wo<<<(NH * NIN) / 256, 256>>>(Wout);
    k_zero<<<(NODES * NH) / 256, 256>>>();

    k_steps<<<256, 256, SMEM_TOT>>>(bout, out);
}